// round 9
// baseline (speedup 1.0000x reference)
#include <cuda_runtime.h>
#include <cstdint>
#include <math.h>

#define EMBED   256
#define HIDDEN  512
#define NB      64
#define LSTEPS  2048

// xp[t][n][h] scratch: 2048*64*512 floats = 256MB
__device__ float g_xp[(size_t)LSTEPS * NB * HIDDEN];

// ---- packed f32x2 helpers (Blackwell) ----
#define FMA_F32X2(acc, a, b) \
    asm("fma.rn.f32x2 %0, %1, %2, %0;" : "+l"(acc) : "l"(a), "l"(b))
#define PACK_F32X2(out, lo, hi) \
    asm("mov.b64 %0, {%1, %2};" : "=l"(out) : "f"(lo), "f"(hi))
#define UNPACK_F32X2(lo, hi, in) \
    asm("mov.b64 {%0, %1}, %2;" : "=f"(lo), "=f"(hi) : "l"(in))

// ============================================================================
// Phase 1: xp[l][n][j] = b_xh[j] + sum_d E[X[n][l]][d] * W_xh[d][j]
// (unchanged — passing, ~0.85ms)
// ============================================================================
#define BM 128
#define BN 128
#define BK 16

__global__ void __launch_bounds__(256)
proj_kernel(const int* __restrict__ X, const float* __restrict__ E,
            const float* __restrict__ Wxh, const float* __restrict__ bxh)
{
    __shared__ float As[BK][BM];
    __shared__ float Bs[BK][BN];
    __shared__ int   toks[BM];

    const int tid   = threadIdx.x;
    const int mtile = blockIdx.y;
    const int n     = mtile >> 4;
    const int l0    = (mtile & 15) * BM;
    const int j0    = blockIdx.x * BN;

    if (tid < BM) toks[tid] = X[n * LSTEPS + l0 + tid];
    __syncthreads();

    const int ty = tid >> 4;
    const int tx = tid & 15;

    unsigned long long acc[8][4];
#pragma unroll
    for (int i = 0; i < 8; i++)
#pragma unroll
        for (int j = 0; j < 4; j++) acc[i][j] = 0ULL;

    for (int k0 = 0; k0 < EMBED; k0 += BK) {
#pragma unroll
        for (int u = 0; u < 2; u++) {
            int f  = tid + u * 256;
            int m  = f & 127;
            int kq = f >> 7;
            float4 v = *(const float4*)&E[(size_t)toks[m] * EMBED + k0 + kq * 4];
            As[kq * 4 + 0][m] = v.x;
            As[kq * 4 + 1][m] = v.y;
            As[kq * 4 + 2][m] = v.z;
            As[kq * 4 + 3][m] = v.w;
        }
#pragma unroll
        for (int u = 0; u < 2; u++) {
            int f  = tid + u * 256;
            int kk = f >> 5;
            int jj = (f & 31) * 4;
            *(float4*)&Bs[kk][jj] =
                *(const float4*)&Wxh[(size_t)(k0 + kk) * HIDDEN + j0 + jj];
        }
        __syncthreads();
#pragma unroll
        for (int kk = 0; kk < BK; kk++) {
            float a[8];
            *(float4*)&a[0] = *(const float4*)&As[kk][ty * 8];
            *(float4*)&a[4] = *(const float4*)&As[kk][ty * 8 + 4];
            ulonglong2 b01 = *(const ulonglong2*)&Bs[kk][tx * 8];
            ulonglong2 b23 = *(const ulonglong2*)&Bs[kk][tx * 8 + 4];
            unsigned long long bp[4] = {b01.x, b01.y, b23.x, b23.y};
#pragma unroll
            for (int i = 0; i < 8; i++) {
                unsigned long long aa;
                PACK_F32X2(aa, a[i], a[i]);
#pragma unroll
                for (int j = 0; j < 4; j++)
                    FMA_F32X2(acc[i][j], aa, bp[j]);
            }
        }
        __syncthreads();
    }

    float bx[8];
#pragma unroll
    for (int q = 0; q < 8; q++) bx[q] = bxh[j0 + tx * 8 + q];

#pragma unroll
    for (int i = 0; i < 8; i++) {
        int l = l0 + ty * 8 + i;
        float* dst = g_xp + (size_t)l * (NB * HIDDEN) + n * HIDDEN + j0 + tx * 8;
        float r[8];
#pragma unroll
        for (int j = 0; j < 4; j++) {
            float lo, hi;
            UNPACK_F32X2(lo, hi, acc[i][j]);
            r[j * 2]     = lo + bx[j * 2];
            r[j * 2 + 1] = hi + bx[j * 2 + 1];
        }
        *(float4*)dst       = make_float4(r[0], r[1], r[2], r[3]);
        *(float4*)(dst + 4) = make_float4(r[4], r[5], r[6], r[7]);
    }
}

// ============================================================================
// Phase 2: persistent cluster RNN, 16 clusters x 8 CTAs (128 SMs), G=4 groups.
// Cluster g owns rows 4g..4g+3 (one per group). CTA rank r owns j-slice
// [64r, 64r+64). W slice ENTIRELY in registers: thread (kg=tid>>5 over 64 k,
// jp=tid&31 over a j-pair) holds 64 packed f32x2 = 128 regs. No W smem.
// Per group: R6-proven monolithic sync (red -> bar -> reduce+tanh+push ->
// bar -> arrive x8 -> wait-next-step), 4 groups interleaved to hide latency.
// ============================================================================
#define CL   8
#define GRP  4
#define JSL  64

struct SmemR {
    float hbuf[GRP][2][HIDDEN];          // [group][buf][j]   16384 B
    float red[GRP][8][JSL];              // [group][kg][j]     8192 B
    float bh[JSL];                       //                     256 B
    unsigned long long mb[GRP];          // per-group mbarrier
};

__device__ __forceinline__ uint32_t smem_u32(const void* p) {
    uint32_t a;
    asm("{ .reg .u64 t; cvta.to.shared.u64 t, %1; cvt.u32.u64 %0, t; }"
        : "=r"(a) : "l"(p));
    return a;
}
__device__ __forceinline__ uint32_t mapa_u32(uint32_t a, uint32_t rank) {
    uint32_t r;
    asm("mapa.shared::cluster.u32 %0, %1, %2;" : "=r"(r) : "r"(a), "r"(rank));
    return r;
}
__device__ __forceinline__ void stc_b32(uint32_t a, float v) {
    asm volatile("st.shared::cluster.b32 [%0], %1;"
                 :: "r"(a), "r"(__float_as_uint(v)) : "memory");
}
__device__ __forceinline__ void mbar_init(uint32_t a, uint32_t cnt) {
    asm volatile("mbarrier.init.shared.b64 [%0], %1;" :: "r"(a), "r"(cnt) : "memory");
}
__device__ __forceinline__ void mbar_arrive_remote(uint32_t a) {
    asm volatile("mbarrier.arrive.release.cluster.shared::cluster.b64 _, [%0];"
                 :: "r"(a) : "memory");
}
__device__ __forceinline__ void mbar_wait_parity(uint32_t a, uint32_t parity) {
    asm volatile(
        "{\n\t.reg .pred P;\n\t"
        "WL_%=:\n\t"
        "mbarrier.try_wait.parity.acquire.cluster.shared::cta.b64 P, [%0], %1, 0x989680;\n\t"
        "@!P bra WL_%=;\n\t}"
        :: "r"(a), "r"(parity) : "memory");
}
__device__ __forceinline__ void cluster_sync_() {
    asm volatile("barrier.cluster.arrive.aligned;" ::: "memory");
    asm volatile("barrier.cluster.wait.aligned;" ::: "memory");
}

// tanh = (e-1)/(e+1), e = 2^(2x*log2e); ~1e-6 abs err, branch-free.
__device__ __forceinline__ float fast_tanh(float x) {
    x = fminf(fmaxf(x, -15.0f), 15.0f);
    float e;
    asm("ex2.approx.f32 %0, %1;" : "=f"(e) : "f"(x * 2.8853900817779268f));
    float r;
    asm("rcp.approx.f32 %0, %1;" : "=f"(r) : "f"(e + 1.0f));
    return (e - 1.0f) * r;
}

__global__ void __cluster_dims__(CL, 1, 1) __launch_bounds__(256, 1)
rnn_kernel(const float* __restrict__ Whh, const float* __restrict__ bhh,
           float* __restrict__ out)
{
    __shared__ SmemR s;
    const int tid  = threadIdx.x;
    const int rank = blockIdx.x;      // 0..7
    const int g    = blockIdx.y;      // 0..15
    const int j0   = rank * JSL;
    const int row0 = 4 * g;

    const int kg = tid >> 5;          // warp id = k-group (64 k each)
    const int jp = tid & 31;          // j-pair: jcol = j0 + jp*2

    // ---- W slice fully in registers: 64 packed f32x2 = 128 regs ----
    // Wr0[m] = (W[kb+2m][c0], W[kb+2m+1][c0]); Wr1[m] same for c1. m=0..31.
    unsigned long long Wr0[32], Wr1[32];
    {
        const int kb   = kg * 64;
        const int jcol = j0 + jp * 2;
#pragma unroll
        for (int m = 0; m < 32; m++) {
            int k = kb + m * 2;
            float2 w0 = *(const float2*)&Whh[(size_t)k * HIDDEN + jcol];
            float2 w1 = *(const float2*)&Whh[(size_t)(k + 1) * HIDDEN + jcol];
            PACK_F32X2(Wr0[m], w0.x, w1.x);
            PACK_F32X2(Wr1[m], w0.y, w1.y);
        }
    }

    // ---- smem init ----
    for (int idx = tid; idx < GRP * 2 * HIDDEN; idx += 256)
        ((float*)s.hbuf)[idx] = 0.f;
    if (tid < JSL) s.bh[tid] = bhh[j0 + tid];

    const uint32_t s_base = smem_u32(&s);
    uint32_t hb_off[GRP], mb_off[GRP];
#pragma unroll
    for (int q = 0; q < GRP; q++) {
        hb_off[q] = smem_u32(&s.hbuf[q][0][0]) - s_base;
        mb_off[q] = smem_u32(&s.mb[q]) - s_base;
    }

    uint32_t peer_base[CL];
#pragma unroll
    for (int r = 0; r < CL; r++) peer_base[r] = mapa_u32(s_base, (uint32_t)r);

    if (tid == 0) {
#pragma unroll
        for (int q = 0; q < GRP; q++) mbar_init(s_base + mb_off[q], CL);
        asm volatile("fence.mbarrier_init.release.cluster;" ::: "memory");
    }
    __syncthreads();
    cluster_sync_();   // hbuf/bh/mbar visible cluster-wide

    // producer role: tid < 64 handles j = tid
    const int rj = tid & 63;
    const bool is_red = (tid < JSL);

    const size_t xstride = (size_t)NB * HIDDEN;
    const float* xp0 = g_xp + (size_t)row0 * HIDDEN + j0 + rj;

    float xcur[GRP], xnxt[GRP];
    const float* xnp[GRP];
#pragma unroll
    for (int q = 0; q < GRP; q++) {
        const float* p = xp0 + (size_t)q * HIDDEN;
        xcur[q] = __ldcs(p);
        xnp[q]  = p + xstride;
    }

    for (int t = 0; t < LSTEPS; t++) {
        const int cur = t & 1;
        const int nxt = cur ^ 1;
        const uint32_t pw = (uint32_t)((t & 1) ^ 1);   // parity of step t-1
        const bool last = (t == LSTEPS - 1);
#pragma unroll
        for (int q = 0; q < GRP; q++)
            xnxt[q] = last ? 0.f : __ldcs(xnp[q]);

#pragma unroll
        for (int grp = 0; grp < GRP; grp++) {
            if (t) mbar_wait_parity(s_base + mb_off[grp], pw);

            // ---- inner product: 1 row x 2 cols x 64 k ----
            const ulonglong2* hv =
                (const ulonglong2*)&s.hbuf[grp][cur][kg * 64];
            unsigned long long a0 = 0ULL, a1 = 0ULL;
#pragma unroll
            for (int i = 0; i < 16; i++) {
                ulonglong2 h = hv[i];
                FMA_F32X2(a0, Wr0[2 * i],     h.x);
                FMA_F32X2(a0, Wr0[2 * i + 1], h.y);
                FMA_F32X2(a1, Wr1[2 * i],     h.x);
                FMA_F32X2(a1, Wr1[2 * i + 1], h.y);
            }
            {
                float lo, hi, f0, f1;
                UNPACK_F32X2(lo, hi, a0); f0 = lo + hi;
                UNPACK_F32X2(lo, hi, a1); f1 = lo + hi;
                *(float2*)&s.red[grp][kg][jp * 2] = make_float2(f0, f1);
            }
            __syncthreads();

            // ---- reduce + tanh + push (tid < 64) ----
            if (is_red) {
                float sum = s.bh[rj] + xcur[grp];
#pragma unroll
                for (int w = 0; w < 8; w++) sum += s.red[grp][w][rj];
                float hn = fast_tanh(sum);

                if (last) {
                    out[(row0 + grp) * HIDDEN + j0 + rj] = hn;
                } else {
                    const uint32_t off = hb_off[grp] +
                        (uint32_t)((nxt * HIDDEN + j0 + rj) * 4);
#pragma unroll
                    for (int r = 0; r < CL; r++)
                        stc_b32(peer_base[r] + off, hn);
                }
            }
            __syncthreads();
            if (!last && tid < CL)
                mbar_arrive_remote(peer_base[tid] + mb_off[grp]);
        }

#pragma unroll
        for (int q = 0; q < GRP; q++) {
            xcur[q] = xnxt[q];
            xnp[q] += xstride;
        }
    }
}

// ============================================================================
extern "C" void kernel_launch(void* const* d_in, const int* in_sizes, int n_in,
                              void* d_out, int out_size)
{
    const int*   X   = (const int*)d_in[0];
    const float* E   = (const float*)d_in[1];
    const float* Whh = (const float*)d_in[2];
    const float* bhh = (const float*)d_in[3];
    const float* Wxh = (const float*)d_in[4];
    const float* bxh = (const float*)d_in[5];
    float* out = (float*)d_out;

    proj_kernel<<<dim3(4, 1024), 256>>>(X, E, Wxh, bxh);
    rnn_kernel<<<dim3(CL, NB / GRP), 256>>>(Whh, bhh, out);
}

// round 10
// speedup vs baseline: 1.9268x; 1.9268x over previous
#include <cuda_runtime.h>
#include <cstdint>
#include <math.h>

#define EMBED   256
#define HIDDEN  512
#define NB      64
#define LSTEPS  2048

// xp[t][n][h] scratch: 2048*64*512 floats = 256MB
__device__ float g_xp[(size_t)LSTEPS * NB * HIDDEN];

// ---- packed f32x2 helpers (Blackwell) ----
#define FMA_F32X2(acc, a, b) \
    asm("fma.rn.f32x2 %0, %1, %2, %0;" : "+l"(acc) : "l"(a), "l"(b))
#define PACK_F32X2(out, lo, hi) \
    asm("mov.b64 %0, {%1, %2};" : "=l"(out) : "f"(lo), "f"(hi))
#define UNPACK_F32X2(lo, hi, in) \
    asm("mov.b64 {%0, %1}, %2;" : "=f"(lo), "=f"(hi) : "l"(in))

// ============================================================================
// Phase 1: xp[l][n][j] = b_xh[j] + sum_d E[X[n][l]][d] * W_xh[d][j]
// (unchanged — passing, ~0.85ms)
// ============================================================================
#define BM 128
#define BN 128
#define BK 16

__global__ void __launch_bounds__(256)
proj_kernel(const int* __restrict__ X, const float* __restrict__ E,
            const float* __restrict__ Wxh, const float* __restrict__ bxh)
{
    __shared__ float As[BK][BM];
    __shared__ float Bs[BK][BN];
    __shared__ int   toks[BM];

    const int tid   = threadIdx.x;
    const int mtile = blockIdx.y;
    const int n     = mtile >> 4;
    const int l0    = (mtile & 15) * BM;
    const int j0    = blockIdx.x * BN;

    if (tid < BM) toks[tid] = X[n * LSTEPS + l0 + tid];
    __syncthreads();

    const int ty = tid >> 4;
    const int tx = tid & 15;

    unsigned long long acc[8][4];
#pragma unroll
    for (int i = 0; i < 8; i++)
#pragma unroll
        for (int j = 0; j < 4; j++) acc[i][j] = 0ULL;

    for (int k0 = 0; k0 < EMBED; k0 += BK) {
#pragma unroll
        for (int u = 0; u < 2; u++) {
            int f  = tid + u * 256;
            int m  = f & 127;
            int kq = f >> 7;
            float4 v = *(const float4*)&E[(size_t)toks[m] * EMBED + k0 + kq * 4];
            As[kq * 4 + 0][m] = v.x;
            As[kq * 4 + 1][m] = v.y;
            As[kq * 4 + 2][m] = v.z;
            As[kq * 4 + 3][m] = v.w;
        }
#pragma unroll
        for (int u = 0; u < 2; u++) {
            int f  = tid + u * 256;
            int kk = f >> 5;
            int jj = (f & 31) * 4;
            *(float4*)&Bs[kk][jj] =
                *(const float4*)&Wxh[(size_t)(k0 + kk) * HIDDEN + j0 + jj];
        }
        __syncthreads();
#pragma unroll
        for (int kk = 0; kk < BK; kk++) {
            float a[8];
            *(float4*)&a[0] = *(const float4*)&As[kk][ty * 8];
            *(float4*)&a[4] = *(const float4*)&As[kk][ty * 8 + 4];
            ulonglong2 b01 = *(const ulonglong2*)&Bs[kk][tx * 8];
            ulonglong2 b23 = *(const ulonglong2*)&Bs[kk][tx * 8 + 4];
            unsigned long long bp[4] = {b01.x, b01.y, b23.x, b23.y};
#pragma unroll
            for (int i = 0; i < 8; i++) {
                unsigned long long aa;
                PACK_F32X2(aa, a[i], a[i]);
#pragma unroll
                for (int j = 0; j < 4; j++)
                    FMA_F32X2(acc[i][j], aa, bp[j]);
            }
        }
        __syncthreads();
    }

    float bx[8];
#pragma unroll
    for (int q = 0; q < 8; q++) bx[q] = bxh[j0 + tx * 8 + q];

#pragma unroll
    for (int i = 0; i < 8; i++) {
        int l = l0 + ty * 8 + i;
        float* dst = g_xp + (size_t)l * (NB * HIDDEN) + n * HIDDEN + j0 + tx * 8;
        float r[8];
#pragma unroll
        for (int j = 0; j < 4; j++) {
            float lo, hi;
            UNPACK_F32X2(lo, hi, acc[i][j]);
            r[j * 2]     = lo + bx[j * 2];
            r[j * 2 + 1] = hi + bx[j * 2 + 1];
        }
        *(float4*)dst       = make_float4(r[0], r[1], r[2], r[3]);
        *(float4*)(dst + 4) = make_float4(r[4], r[5], r[6], r[7]);
    }
}

// ============================================================================
// Phase 2: persistent cluster RNN, 32 clusters x 4 CTAs, FUSED two rows.
// Cluster g owns rows {2g, 2g+1}. CTA rank r owns j in [128r, 128r+128).
// Thread (kh = tid>>7, j = tid&127) owns W column-half:
//   W[k][j0+j] for k in [256*kh, 256*kh+256)  -> 64 quads of 4 k.
//   36 quads (72 ull) in registers, 28 quads (56 ull) in smem.
// Both rows computed in ONE pass over W (crossbar traffic halved vs R6).
// 2-way partner reduce via red[2][128], one mbar rendezvous per step.
// ============================================================================
#define CL       4
#define JSL      128
#define RQ       36                     // reg quads (72 ull = 144 reg slots)
#define SQ       28                     // smem quads (56 ull)

struct SmemR {
    ulonglong2 Wsm[SQ * 256];           // [quad][tid]          114688 B
    float hbuf[2][2][HIDDEN];           // [row(kh)][buf][j]      8192 B
    float red[2][JSL];                  // cross-half partials    1024 B
    float bh[JSL];                      //                         512 B
    unsigned long long mb;              // rendezvous mbarrier
};
#define SMEMR_BYTES ((int)sizeof(SmemR))

__device__ __forceinline__ uint32_t smem_u32(const void* p) {
    uint32_t a;
    asm("{ .reg .u64 t; cvta.to.shared.u64 t, %1; cvt.u32.u64 %0, t; }"
        : "=r"(a) : "l"(p));
    return a;
}
__device__ __forceinline__ uint32_t mapa_u32(uint32_t a, uint32_t rank) {
    uint32_t r;
    asm("mapa.shared::cluster.u32 %0, %1, %2;" : "=r"(r) : "r"(a), "r"(rank));
    return r;
}
__device__ __forceinline__ void stc_f32x2(uint32_t a, float v0, float v1) {
    asm volatile("st.shared::cluster.v2.f32 [%0], {%1,%2};"
                 :: "r"(a), "f"(v0), "f"(v1) : "memory");
}
__device__ __forceinline__ void mbar_init(uint32_t a, uint32_t cnt) {
    asm volatile("mbarrier.init.shared.b64 [%0], %1;" :: "r"(a), "r"(cnt) : "memory");
}
__device__ __forceinline__ void mbar_arrive_remote(uint32_t a) {
    asm volatile("mbarrier.arrive.release.cluster.shared::cluster.b64 _, [%0];"
                 :: "r"(a) : "memory");
}
__device__ __forceinline__ void mbar_wait_parity(uint32_t a, uint32_t parity) {
    asm volatile(
        "{\n\t.reg .pred P;\n\t"
        "WL_%=:\n\t"
        "mbarrier.try_wait.parity.acquire.cluster.shared::cta.b64 P, [%0], %1, 0x989680;\n\t"
        "@!P bra WL_%=;\n\t}"
        :: "r"(a), "r"(parity) : "memory");
}
__device__ __forceinline__ void cluster_sync_() {
    asm volatile("barrier.cluster.arrive.aligned;" ::: "memory");
    asm volatile("barrier.cluster.wait.aligned;" ::: "memory");
}

// tanh = (e-1)/(e+1), e = 2^(2x*log2e); ~1e-6 abs err, branch-free.
__device__ __forceinline__ float fast_tanh(float x) {
    x = fminf(fmaxf(x, -15.0f), 15.0f);
    float e;
    asm("ex2.approx.f32 %0, %1;" : "=f"(e) : "f"(x * 2.8853900817779268f));
    float r;
    asm("rcp.approx.f32 %0, %1;" : "=f"(r) : "f"(e + 1.0f));
    return (e - 1.0f) * r;
}

extern __shared__ float smem_raw[];

__global__ void __cluster_dims__(CL, 1, 1) __launch_bounds__(256, 1)
rnn_kernel(const float* __restrict__ Whh, const float* __restrict__ bhh,
           float* __restrict__ out)
{
    SmemR* s = (SmemR*)smem_raw;
    const int tid  = threadIdx.x;
    const int rank = blockIdx.x;      // 0..3
    const int g    = blockIdx.y;      // 0..31
    const int j0   = rank * JSL;

    const int kh = tid >> 7;          // k-half: 0 -> k[0,256), 1 -> k[256,512)
    const int j  = tid & 127;         // owned column within slice
    const int jcol = j0 + j;
    const int kb   = kh * 256;

    // ---- W column-half: quads 0..RQ-1 in regs, RQ..63 in smem ----
    // quad i covers k = kb+4i..kb+4i+3; Wq[2i]=(W[kb+4i][j],W[kb+4i+1][j]),
    // Wq[2i+1]=(W[kb+4i+2][j],W[kb+4i+3][j]).
    unsigned long long Wq[2 * RQ];
#pragma unroll
    for (int i = 0; i < RQ; i++) {
#pragma unroll
        for (int p = 0; p < 2; p++) {
            int k = kb + 4 * i + 2 * p;
            float w0 = Whh[(size_t)k * HIDDEN + jcol];
            float w1 = Whh[(size_t)(k + 1) * HIDDEN + jcol];
            PACK_F32X2(Wq[2 * i + p], w0, w1);
        }
    }
#pragma unroll
    for (int i = 0; i < SQ; i++) {
        unsigned long long u[2];
#pragma unroll
        for (int p = 0; p < 2; p++) {
            int k = kb + 4 * (RQ + i) + 2 * p;
            float w0 = Whh[(size_t)k * HIDDEN + jcol];
            float w1 = Whh[(size_t)(k + 1) * HIDDEN + jcol];
            PACK_F32X2(u[p], w0, w1);
        }
        s->Wsm[i * 256 + tid] = make_ulonglong2(u[0], u[1]);
    }

    // ---- smem init ----
    for (int idx = tid; idx < 2 * 2 * HIDDEN; idx += 256)
        ((float*)s->hbuf)[idx] = 0.f;
    if (tid < JSL) s->bh[tid] = bhh[j0 + tid];

    const uint32_t s_base = smem_u32(s);
    const uint32_t mb_off = smem_u32(&s->mb) - s_base;
    const uint32_t hb_off = smem_u32(&s->hbuf[kh][0][0]) - s_base;  // own row

    uint32_t peer_base[CL];
#pragma unroll
    for (int r = 0; r < CL; r++) peer_base[r] = mapa_u32(s_base, (uint32_t)r);

    if (tid == 0) {
        mbar_init(s_base + mb_off, CL);
        asm volatile("fence.mbarrier_init.release.cluster;" ::: "memory");
    }
    __syncthreads();
    cluster_sync_();   // W/h/bh/mbar visible cluster-wide

    // this thread finalizes row (2g + kh), column jcol
    const int myrow = 2 * g + kh;
    const size_t xstride = (size_t)NB * HIDDEN;
    const float* xp_ptr = g_xp + (size_t)myrow * HIDDEN + jcol;

    float xcur = __ldcs(xp_ptr);
    const float* xnp = xp_ptr + xstride;

    const int lane = tid & 31;
    const int je   = j & ~1;          // even-j push base

    const ulonglong2* WsmT = &s->Wsm[tid];    // quad i at WsmT[i*256]

    for (int t = 0; t < LSTEPS; t++) {
        const int cur = t & 1;
        const int nxt = cur ^ 1;
        const bool last = (t == LSTEPS - 1);
        float xnxt = last ? 0.f : __ldcs(xnp);

        if (t) mbar_wait_parity(s_base + mb_off, (uint32_t)((t & 1) ^ 1));

        // ---- fused inner product: both rows, one W pass ----
        const ulonglong2* hA = (const ulonglong2*)&s->hbuf[0][cur][kb];
        const ulonglong2* hB = (const ulonglong2*)&s->hbuf[1][cur][kb];

        unsigned long long aA = 0ULL, aB = 0ULL;
#pragma unroll
        for (int i = 0; i < RQ; i++) {
            ulonglong2 ha = hA[i];
            ulonglong2 hb = hB[i];
            FMA_F32X2(aA, Wq[2 * i],     ha.x);
            FMA_F32X2(aA, Wq[2 * i + 1], ha.y);
            FMA_F32X2(aB, Wq[2 * i],     hb.x);
            FMA_F32X2(aB, Wq[2 * i + 1], hb.y);
        }
#pragma unroll
        for (int i = 0; i < SQ; i++) {
            ulonglong2 w  = WsmT[i * 256];
            ulonglong2 ha = hA[RQ + i];
            ulonglong2 hb = hB[RQ + i];
            FMA_F32X2(aA, w.x, ha.x);
            FMA_F32X2(aA, w.y, ha.y);
            FMA_F32X2(aB, w.x, hb.x);
            FMA_F32X2(aB, w.y, hb.y);
        }

        float lo, hi, fA, fB;
        UNPACK_F32X2(lo, hi, aA); fA = lo + hi;
        UNPACK_F32X2(lo, hi, aB); fB = lo + hi;

        // 2-way partner reduce: kh=0 finalizes row A, kh=1 row B.
        // red[0][j] = A-partial from kh=1; red[1][j] = B-partial from kh=0.
        s->red[1 - kh][j] = kh ? fA : fB;
        __syncthreads();
        float own   = kh ? fB : fA;
        float other = s->red[kh][j];
        float hn = fast_tanh(s->bh[j] + xcur + own + other);

        if (last) {
            out[myrow * HIDDEN + jcol] = hn;
        } else {
            // paired float2 push of (even j, odd j) to own row's hbuf[nxt]
            float hj = __shfl_xor_sync(0xffffffffu, hn, 1);
            if ((lane & 1) == 0) {
                float v0 = hn, v1 = hj;
                const uint32_t off =
                    hb_off + (uint32_t)((nxt * HIDDEN + j0 + je) * 4);
#pragma unroll
                for (int r = 0; r < CL; r++)
                    stc_f32x2(peer_base[r] + off, v0, v1);
            }
            __syncthreads();
            if (tid < CL)
                mbar_arrive_remote(peer_base[tid] + mb_off);
        }

        xcur = xnxt;
        xnp += xstride;
    }
}

// ============================================================================
extern "C" void kernel_launch(void* const* d_in, const int* in_sizes, int n_in,
                              void* d_out, int out_size)
{
    const int*   X   = (const int*)d_in[0];
    const float* E   = (const float*)d_in[1];
    const float* Whh = (const float*)d_in[2];
    const float* bhh = (const float*)d_in[3];
    const float* Wxh = (const float*)d_in[4];
    const float* bxh = (const float*)d_in[5];
    float* out = (float*)d_out;

    cudaFuncSetAttribute(rnn_kernel,
                         cudaFuncAttributeMaxDynamicSharedMemorySize,
                         SMEMR_BYTES);

    proj_kernel<<<dim3(4, 1024), 256>>>(X, E, Wxh, bxh);
    rnn_kernel<<<dim3(CL, NB / 2), 256, SMEMR_BYTES>>>(Whh, bhh, out);
}